// round 7
// baseline (speedup 1.0000x reference)
#include <cuda_runtime.h>

typedef unsigned int u32;
typedef unsigned long long u64;

static constexpr int Bn  = 4;
static constexpr int Sn  = 4000;
static constexpr int Din = 1024;
static constexpr int Da  = 512;
static constexpr int Ln  = 8921;
static constexpr int M2  = 2 * Ln;       // 17842 rows: [U; V]
static constexpr int M2pad = 17920;      // 140 * 128
static constexpr int Spad  = 4096;       // padded seq per batch for GEMM2 B

// ---- scratch (device globals; no allocation allowed) ----
__device__ float g_xr [(u64)Bn * Sn * Din];       // x rounded to tf32 (row-major)
__device__ float g_wr [(u64)Da * Din];            // W_w rounded (row-major)
__device__ float g_uv2[(u64)M2pad * Da];          // [U; V] tf32, fragment-permuted rows
__device__ float g_z2 [(u64)Bn * Spad * Da];      // z tf32, fragment-permuted rows, padded
__device__ float g_w  [(u64)Bn * Ln * Sn];        // w = V z^T (571 MB)

// single dynamic-shared declaration shared by all kernels
extern __shared__ __align__(1024) char dyn_smem[];

// ---- helpers ----
__device__ __forceinline__ u32 f2tf(float f) {
    u32 u;
    asm("cvt.rna.tf32.f32 %0, %1;" : "=r"(u) : "f"(f));
    return u;
}

__device__ __forceinline__ void cp16(u32 saddr, const void* g) {
    asm volatile("cp.async.cg.shared.global [%0], [%1], 16;\n" :: "r"(saddr), "l"(g));
}

__device__ __forceinline__ void mma8(float* c, u32 a0, u32 a1, u32 a2, u32 a3,
                                     u32 b0, u32 b1) {
    asm volatile(
        "mma.sync.aligned.m16n8k8.row.col.f32.tf32.tf32.f32 "
        "{%0,%1,%2,%3}, {%4,%5,%6,%7}, {%8,%9}, {%0,%1,%2,%3};\n"
        : "+f"(c[0]), "+f"(c[1]), "+f"(c[2]), "+f"(c[3])
        : "r"(a0), "r"(a1), "r"(a2), "r"(a3), "r"(b0), "r"(b1));
}

#define LDS128(v, addr) \
    asm volatile("ld.shared.v4.b32 {%0,%1,%2,%3}, [%4];" \
        : "=r"((v)[0]), "=r"((v)[1]), "=r"((v)[2]), "=r"((v)[3]) : "r"(addr))

// ---- input rounding ----
// sel 0/1: row-major copy+round (x, W). sel 2/3: fragment-permuted rows (U, V).
__global__ void round_k(const float* __restrict__ in, int n4, int sel) {
    int i = blockIdx.x * blockDim.x + threadIdx.x;
    if (i >= n4) return;
    float4 v = ((const float4*)in)[i];
    u32 rx = f2tf(v.x), ry = f2tf(v.y), rz = f2tf(v.z), rw = f2tf(v.w);
    if (sel <= 1) {
        float* out = (sel == 0) ? g_xr : g_wr;
        uint4 o; o.x = rx; o.y = ry; o.z = rz; o.w = rw;
        ((uint4*)out)[i] = o;
    } else {
        float* out = (sel == 2) ? g_uv2 : (g_uv2 + (u64)Ln * Da);
        const int f = i * 4;                 // k multiple of 4
        const int row = f >> 9;              // /512
        const int k   = f & 511;
        u32* base = (u32*)(out + (u64)row * Da + (k >> 2));
        base[0]   = rx;  base[128] = ry;  base[256] = rz;  base[384] = rw;
    }
}

// ---- GEMM1 (mma.sync): z = tanh(x W^T + b) -> g_z2 (permuted, padded) ----
static constexpr int BM = 128, BN = 128, BK = 32, KS = 36;
static constexpr int TILEF = BM * KS;
static constexpr u32 SMEM1_BYTES = 4u * TILEF * 4u;

__global__ void __launch_bounds__(256, 2)
gemm1_k(const float* __restrict__ bias) {
    constexpr int K   = Din;
    constexpr int KIT = K / BK;

    float* smem = (float*)dyn_smem;
    float* As = smem;
    float* Bs = smem + 2 * TILEF;

    const int tid   = threadIdx.x;
    const int nbase = blockIdx.x * BN;
    const int mbase = blockIdx.y * BM;

    const int lr = tid >> 3;
    const int lc = (tid & 7) * 4;
    const float* aG = g_xr + (u64)(mbase + lr) * K + lc;
    const float* bG = g_wr + (u64)(nbase + lr) * K + lc;

    u32 sA = (u32)__cvta_generic_to_shared(As + lr * KS + lc);
    u32 sB = (u32)__cvta_generic_to_shared(Bs + lr * KS + lc);
    const u32 bufB = (u32)TILEF * 4u;

    auto issue = [&](int kt, int buf) {
        const float* a = aG + kt * BK;
        const float* b = bG + kt * BK;
#pragma unroll
        for (int i = 0; i < 4; i++) cp16(sA + buf * bufB + i * (32 * KS * 4), a + (u64)i * 32 * K);
#pragma unroll
        for (int i = 0; i < 4; i++) cp16(sB + buf * bufB + i * (32 * KS * 4), b + (u64)i * 32 * K);
    };

    issue(0, 0); asm volatile("cp.async.commit_group;\n");
    issue(1, 1); asm volatile("cp.async.commit_group;\n");

    const int warp = tid >> 5, lane = tid & 31;
    const int g = lane >> 2, tg = lane & 3;
    const int wm = warp & 3, wn = warp >> 2;

    float c[2][8][4];
#pragma unroll
    for (int mf = 0; mf < 2; mf++)
#pragma unroll
        for (int nf = 0; nf < 8; nf++)
#pragma unroll
            for (int i = 0; i < 4; i++) c[mf][nf][i] = 0.f;

    for (int kt = 0; kt < KIT; kt++) {
        if (kt == KIT - 1) asm volatile("cp.async.wait_group 0;\n");
        else               asm volatile("cp.async.wait_group 1;\n");
        __syncthreads();

        const float* as = As + (kt & 1) * TILEF + (wm * 32) * KS;
        const float* bs = Bs + (kt & 1) * TILEF + (wn * 64) * KS;
#pragma unroll
        for (int ks = 0; ks < 4; ks++) {
            const int k0 = ks * 8;
            u32 a[2][4];
#pragma unroll
            for (int mf = 0; mf < 2; mf++) {
                const float* ar = as + (mf * 16) * KS;
                a[mf][0] = __float_as_uint(ar[(g    ) * KS + k0 + tg    ]);
                a[mf][1] = __float_as_uint(ar[(g + 8) * KS + k0 + tg    ]);
                a[mf][2] = __float_as_uint(ar[(g    ) * KS + k0 + tg + 4]);
                a[mf][3] = __float_as_uint(ar[(g + 8) * KS + k0 + tg + 4]);
            }
#pragma unroll
            for (int nf = 0; nf < 8; nf++) {
                u32 b0 = __float_as_uint(bs[(nf * 8 + g) * KS + k0 + tg    ]);
                u32 b1 = __float_as_uint(bs[(nf * 8 + g) * KS + k0 + tg + 4]);
                mma8(c[0][nf], a[0][0], a[0][1], a[0][2], a[0][3], b0, b1);
                mma8(c[1][nf], a[1][0], a[1][1], a[1][2], a[1][3], b0, b1);
            }
        }
        __syncthreads();
        if (kt + 2 < KIT) { issue(kt + 2, kt & 1); asm volatile("cp.async.commit_group;\n"); }
    }

    // epilogue: tanh(+bias), tf32 round, store permuted+padded into g_z2
#pragma unroll
    for (int mf = 0; mf < 2; mf++) {
#pragma unroll
        for (int nf = 0; nf < 8; nf++) {
            const int r  = mbase + wm * 32 + mf * 16 + g;   // 0..15999
            const int cl = nbase + wn * 64 + nf * 8 + 2 * tg;
            float* cc = c[mf][nf];
            const float b0 = bias[cl], b1 = bias[cl + 1];
            const int c0 = cl & 3, j = cl >> 2;
#pragma unroll
            for (int rr = 0; rr < 2; rr++) {
                const int row = r + rr * 8;
                const int b   = row / Sn;
                const int s   = row - b * Sn;
                u32* dst = (u32*)(g_z2 + ((u64)b * Spad + s) * Da + j);
                dst[c0 * 128]       = f2tf(tanhf(cc[rr * 2 + 0] + b0));
                dst[(c0 + 1) * 128] = f2tf(tanhf(cc[rr * 2 + 1] + b1));
            }
        }
    }
}

// ---- GEMM2 (mma.sync, permuted layout, 128x128 tile, 2 CTAs/SM) ----
static constexpr int G2_BM = 128, G2_BN = 128;
static constexpr int G2_STAGES = 3;
static constexpr int G2_KIT = Da / 32;                    // 16
static constexpr u32 G2_AB  = (u32)G2_BM * 128u;          // 16384
static constexpr u32 G2_ST  = G2_AB + (u32)G2_BN * 128u;  // 32768
static constexpr u32 G2_SMEM = G2_ST * G2_STAGES;         // 98304

__global__ void __launch_bounds__(256, 2)
gemm2_k(float* __restrict__ dout) {
    const u32 sb = (u32)__cvta_generic_to_shared(dyn_smem);
    const int tid  = threadIdx.x;
    const int warp = tid >> 5, lane = tid & 31;
    const int g = lane >> 2, tg = lane & 3;
    const int wm = warp & 3, wn = warp >> 2;   // 4(M) x 2(N); warp tile 32x64
    const int nbase = blockIdx.x * G2_BN;
    const int mbase = blockIdx.y * G2_BM;
    const int bz    = blockIdx.z;

    // cp.async granule assignment: A 4/thread, B 4/thread (16B each)
    const float* Bg = g_z2 + (u64)bz * Spad * Da;
    u32 adst[4]; const float* asrc[4];
    u32 bdst[4]; const float* bsrc[4];
#pragma unroll
    for (int i = 0; i < 4; i++) {
        const int gi = tid + i * 256;            // 0..1023
        const int r = gi >> 3, s = gi & 7;
        const u32 off = (u32)(r * 128 + ((s ^ (r & 7)) << 4));
        adst[i] = off;
        bdst[i] = G2_AB + off;
        asrc[i] = g_uv2 + (u64)(mbase + r) * Da + (s >> 1) * 128 + (s & 1) * 4;
        bsrc[i] = Bg    + (u64)(nbase + r) * Da + (s >> 1) * 128 + (s & 1) * 4;
    }

    auto load = [&](int kt, int st) {
        const u32 base = sb + (u32)st * G2_ST;
        const int ko = kt * 8;
#pragma unroll
        for (int i = 0; i < 4; i++) cp16(base + adst[i], asrc[i] + ko);
#pragma unroll
        for (int i = 0; i < 4; i++) cp16(base + bdst[i], bsrc[i] + ko);
        asm volatile("cp.async.commit_group;\n");
    };

    load(0, 0); load(1, 1); load(2, 2);

    float acc[2][8][4];
#pragma unroll
    for (int mf = 0; mf < 2; mf++)
#pragma unroll
        for (int nf = 0; nf < 8; nf++)
#pragma unroll
            for (int i = 0; i < 4; i++) acc[mf][nf][i] = 0.f;

    for (int kt = 0; kt < G2_KIT; kt++) {
        const int st = kt % G2_STAGES;
        if      (kt <  G2_KIT - 2) asm volatile("cp.async.wait_group 2;\n");
        else if (kt == G2_KIT - 2) asm volatile("cp.async.wait_group 1;\n");
        else                       asm volatile("cp.async.wait_group 0;\n");
        __syncthreads();

        const u32 stb = sb + (u32)st * G2_ST;
#pragma unroll
        for (int h = 0; h < 2; h++) {
            const u32 sw = (u32)(((2 * tg + h) ^ g) << 4);
            const u32 baseA = stb + (u32)((wm * 32 + g) * 128) + sw;
            const u32 baseB = stb + G2_AB + (u32)((wn * 64 + g) * 128) + sw;

            // A fragments: rows g, g+8, g+16, g+24 of the 32-row warp tile
            u32 a[4][4];
#pragma unroll
            for (int q = 0; q < 4; q++)
                LDS128(a[q], baseA + (u32)(q * 8 * 128));

            // B fragments in two quads to bound live registers
#pragma unroll
            for (int half = 0; half < 2; half++) {
                u32 b[4][4];
#pragma unroll
                for (int q = 0; q < 4; q++)
                    LDS128(b[q], baseB + (u32)((half * 4 + q) * 8 * 128));
#pragma unroll
                for (int ksh = 0; ksh < 2; ksh++) {
#pragma unroll
                    for (int mf = 0; mf < 2; mf++)
#pragma unroll
                        for (int q = 0; q < 4; q++)
                            mma8(acc[mf][half * 4 + q],
                                 a[2 * mf][2 * ksh], a[2 * mf + 1][2 * ksh],
                                 a[2 * mf][2 * ksh + 1], a[2 * mf + 1][2 * ksh + 1],
                                 b[q][2 * ksh], b[q][2 * ksh + 1]);
                }
            }
        }
        __syncthreads();
        if (kt + G2_STAGES < G2_KIT) load(kt + G2_STAGES, st);
    }

    // epilogue: rows < Ln -> scores (alpha region of d_out), rows >= Ln -> g_w
#pragma unroll
    for (int mf = 0; mf < 2; mf++) {
#pragma unroll
        for (int nf = 0; nf < 8; nf++) {
            const int cl = nbase + wn * 64 + nf * 8 + 2 * tg;
            if (cl >= Sn) continue;
            const float* cc = acc[mf][nf];
#pragma unroll
            for (int rr = 0; rr < 2; rr++) {
                const int row = mbase + wm * 32 + mf * 16 + rr * 8 + g;
                if (row < M2) {
                    float* dst = (row < Ln)
                        ? (dout + ((u64)bz * Ln + row) * Sn + cl)
                        : (g_w  + ((u64)bz * Ln + (row - Ln)) * Sn + cl);
                    *(float2*)dst = make_float2(cc[rr * 2 + 0], cc[rr * 2 + 1]);
                }
            }
        }
    }
}

// ---- block reduction (256 threads, 8 warps) ----
__device__ __forceinline__ float bred(float v, float* red, bool sum) {
#pragma unroll
    for (int o = 16; o; o >>= 1) {
        float t = __shfl_xor_sync(0xffffffffu, v, o);
        v = sum ? (v + t) : fmaxf(v, t);
    }
    __syncthreads();
    if ((threadIdx.x & 31) == 0) red[threadIdx.x >> 5] = v;
    __syncthreads();
    float out = red[0];
#pragma unroll
    for (int i = 1; i < 8; i++) out = sum ? (out + red[i]) : fmaxf(out, red[i]);
    return out;
}

// ---- finalize: softmax per (b,l) row in place + y ----
__global__ void __launch_bounds__(256)
finalize_k(float* __restrict__ dout, const float* __restrict__ Vb) {
    const int bid = blockIdx.x;
    const int b = bid / Ln;
    const int l = bid - b * Ln;
    float*       arow = dout + (u64)Bn * Ln + ((u64)b * Ln + l) * Sn;
    const float* wrow = g_w  + ((u64)b * Ln + l) * Sn;
    const int tid = threadIdx.x;
    __shared__ float red[8];

    const int base = tid * 4;
    float4 r[4];
    float mx = -3.402823466e38f;
#pragma unroll
    for (int j = 0; j < 4; j++) {
        const int i = base + j * 1024;
        if (i < Sn) {
            r[j] = *(const float4*)(arow + i);
            mx = fmaxf(mx, fmaxf(fmaxf(r[j].x, r[j].y), fmaxf(r[j].z, r[j].w)));
        }
    }
    mx = bred(mx, red, false);

    float s = 0.f;
#pragma unroll
    for (int j = 0; j < 4; j++) {
        const int i = base + j * 1024;
        if (i < Sn) {
            r[j].x = __expf(r[j].x - mx);
            r[j].y = __expf(r[j].y - mx);
            r[j].z = __expf(r[j].z - mx);
            r[j].w = __expf(r[j].w - mx);
            s += r[j].x + r[j].y + r[j].z + r[j].w;
        }
    }
    s = bred(s, red, true);
    const float inv = 1.f / s;

    float y = 0.f;
#pragma unroll
    for (int j = 0; j < 4; j++) {
        const int i = base + j * 1024;
        if (i < Sn) {
            float4 w4 = *(const float4*)(wrow + i);
            float4 a4;
            a4.x = r[j].x * inv; a4.y = r[j].y * inv;
            a4.z = r[j].z * inv; a4.w = r[j].w * inv;
            *(float4*)(arow + i) = a4;
            y += a4.x * w4.x + a4.y * w4.y + a4.z * w4.z + a4.w * w4.w;
        }
    }
    y = bred(y, red, true);
    if (tid == 0) dout[(u64)b * Ln + l] = y + Vb[l];
}

// ---- launch ----
extern "C" void kernel_launch(void* const* d_in, const int* in_sizes, int n_in,
                              void* d_out, int out_size) {
    const float* x  = (const float*)d_in[0];
    const float* Ww = (const float*)d_in[1];
    const float* Wb = (const float*)d_in[2];
    const float* Uw = (const float*)d_in[3];
    const float* Vw = (const float*)d_in[4];
    const float* Vb = (const float*)d_in[5];
    float* out = (float*)d_out;

    cudaFuncSetAttribute(gemm1_k, cudaFuncAttributeMaxDynamicSharedMemorySize, (int)SMEM1_BYTES);
    cudaFuncSetAttribute(gemm2_k, cudaFuncAttributeMaxDynamicSharedMemorySize, (int)G2_SMEM);

    // round inputs to tf32 (float4 element counts)
    round_k<<<(4096000 + 255) / 256, 256>>>(x,  4096000, 0);
    round_k<<<( 131072 + 255) / 256, 256>>>(Ww,  131072, 1);
    round_k<<<(1141888 + 255) / 256, 256>>>(Uw, 1141888, 2);
    round_k<<<(1141888 + 255) / 256, 256>>>(Vw, 1141888, 3);

    // z = tanh(x W^T + b) -> permuted/padded g_z2
    gemm1_k<<<dim3(4, 125, 1), 256, SMEM1_BYTES>>>(Wb);
    // [scores; w] = [U; V] z^T (scores -> alpha region, w -> g_w)
    gemm2_k<<<dim3(32, 140, 4), 256, G2_SMEM>>>(out + (u64)Bn * Ln);
    // softmax rows in place + y
    finalize_k<<<Bn * Ln, 256>>>(out, Vb);
}

// round 10
// speedup vs baseline: 1.3501x; 1.3501x over previous
#include <cuda_runtime.h>

typedef unsigned int u32;
typedef unsigned long long u64;

static constexpr int Bn  = 4;
static constexpr int Sn  = 4000;
static constexpr int Din = 1024;
static constexpr int Da  = 512;
static constexpr int Ln  = 8921;
static constexpr int M2  = 2 * Ln;       // 17842 rows: [U; V]
static constexpr int M2pad = 17920;      // 140 * 128
static constexpr int Zrows = Bn * Sn;    // 16000
static constexpr int Zpad  = Zrows + 128;

// ---- scratch (device globals; no allocation allowed) ----
__device__ float g_xr [(u64)Bn * Sn * Din];   // x rounded to tf32
__device__ float g_wr [(u64)Da * Din];        // W_w rounded
__device__ float g_uvr[(u64)M2pad * Da];      // [U; V] rounded (padded rows)
__device__ float g_z  [(u64)Zpad * Da];       // z = tanh(xW^T+b), tf32-rounded
__device__ float g_w  [(u64)Bn * Ln * Sn];    // w = V z^T (571 MB)

// single dynamic-shared declaration shared by all kernels
extern __shared__ __align__(1024) char dyn_smem[];

// ---- helpers ----
__device__ __forceinline__ u32 f2tf(float f) {
    u32 u;
    asm("cvt.rna.tf32.f32 %0, %1;" : "=r"(u) : "f"(f));
    return u;
}

__device__ __forceinline__ void cp16(u32 saddr, const void* g) {
    asm volatile("cp.async.cg.shared.global [%0], [%1], 16;\n" :: "r"(saddr), "l"(g));
}

__device__ __forceinline__ void mma8(float* c, const u32* a, u32 b0, u32 b1) {
    asm volatile(
        "mma.sync.aligned.m16n8k8.row.col.f32.tf32.tf32.f32 "
        "{%0,%1,%2,%3}, {%4,%5,%6,%7}, {%8,%9}, {%0,%1,%2,%3};\n"
        : "+f"(c[0]), "+f"(c[1]), "+f"(c[2]), "+f"(c[3])
        : "r"(a[0]), "r"(a[1]), "r"(a[2]), "r"(a[3]), "r"(b0), "r"(b1));
}

// ---- input rounding to tf32 ----
__global__ void round_k(const float* __restrict__ in, int n4, int sel) {
    int i = blockIdx.x * blockDim.x + threadIdx.x;
    if (i >= n4) return;
    float* out = (sel == 0) ? g_xr
               : (sel == 1) ? g_wr
               : (sel == 2) ? g_uvr
                            : (g_uvr + (u64)Ln * Da);
    float4 v = ((const float4*)in)[i];
    uint4 o;
    o.x = f2tf(v.x); o.y = f2tf(v.y); o.z = f2tf(v.z); o.w = f2tf(v.w);
    ((uint4*)out)[i] = o;
}

// ---- tiled tf32 GEMM: C[m,n] = sum_k A[m,k]*B[n,k]  (3-stage, 1 sync/iter) ----
// EPI==0: z-GEMM  (A=g_xr [16000,1024], B=g_wr [512,1024]) -> g_z, tanh+bias, tf32 round
// EPI==1: sw-GEMM (A=g_uvr [17920,512], B=g_z(batch) [4000+,512])
//         rows < Ln -> scores into d_out alpha region; rows >= Ln -> g_w
static constexpr int BM = 128, BN = 128, BK = 32, KS = 36;
static constexpr int STAGES = 3;
static constexpr int TILEF = BM * KS;                       // floats per A (or B) buffer
static constexpr u32 SMEM_BYTES = 2u * STAGES * TILEF * 4u; // 110592 B

template<int EPI>
__global__ void __launch_bounds__(256, 2)
gemm_k(const float* __restrict__ bias, float* __restrict__ dout) {
    constexpr int K   = (EPI == 0) ? Din : Da;
    constexpr int KIT = K / BK;

    float* smem = (float*)dyn_smem;
    float* As = smem;                       // 3 stage buffers
    float* Bs = smem + STAGES * TILEF;      // 3 stage buffers

    const int tid   = threadIdx.x;
    const int nbase = blockIdx.x * BN;
    const int mbase = blockIdx.y * BM;
    const int bz    = blockIdx.z;

    const float* Ag = (EPI == 0) ? g_xr : g_uvr;
    const float* Bg = (EPI == 0) ? g_wr : (g_z + (u64)bz * Sn * Da);

    const int lr = tid >> 3;         // 0..31
    const int lc = (tid & 7) * 4;    // 0..28
    const float* aG = Ag + (u64)(mbase + lr) * K + lc;
    const float* bG = Bg + (u64)(nbase + lr) * K + lc;

    u32 sA = (u32)__cvta_generic_to_shared(As + lr * KS + lc);
    u32 sB = (u32)__cvta_generic_to_shared(Bs + lr * KS + lc);
    const u32 bufB = (u32)TILEF * 4u;

    auto issue = [&](int kt, int buf) {
        const float* a = aG + kt * BK;
        const float* b = bG + kt * BK;
#pragma unroll
        for (int i = 0; i < 4; i++) cp16(sA + buf * bufB + i * (32 * KS * 4), a + (u64)i * 32 * K);
#pragma unroll
        for (int i = 0; i < 4; i++) cp16(sB + buf * bufB + i * (32 * KS * 4), b + (u64)i * 32 * K);
        asm volatile("cp.async.commit_group;\n");
    };

    issue(0, 0);
    issue(1, 1);

    const int warp = tid >> 5, lane = tid & 31;
    const int g = lane >> 2, tg = lane & 3;
    const int wm = warp & 3, wn = warp >> 2;   // 4 x 2 warp grid (M x N)

    float c[2][8][4];
#pragma unroll
    for (int mf = 0; mf < 2; mf++)
#pragma unroll
        for (int nf = 0; nf < 8; nf++)
#pragma unroll
            for (int i = 0; i < 4; i++) c[mf][nf][i] = 0.f;

    for (int kt = 0; kt < KIT; kt++) {
        const int st = kt % STAGES;
        // ensure tile kt's cp.async group has landed
        if (kt == KIT - 1) asm volatile("cp.async.wait_group 0;\n");
        else               asm volatile("cp.async.wait_group 1;\n");
        // single barrier per iteration: makes tile kt visible to all warps AND
        // guarantees everyone finished reading the slot that the load below overwrites
        __syncthreads();

        // prefetch tile kt+2 into slot (kt+2)%3 (last read in iter kt-1)
        if (kt + 2 < KIT) issue(kt + 2, (kt + 2) % STAGES);

        const float* as = As + st * TILEF + (wm * 32) * KS;
        const float* bs = Bs + st * TILEF + (wn * 64) * KS;
#pragma unroll
        for (int ks = 0; ks < 4; ks++) {
            const int k0 = ks * 8;
            u32 a[2][4];
#pragma unroll
            for (int mf = 0; mf < 2; mf++) {
                const float* ar = as + (mf * 16) * KS;
                a[mf][0] = __float_as_uint(ar[(g    ) * KS + k0 + tg    ]);
                a[mf][1] = __float_as_uint(ar[(g + 8) * KS + k0 + tg    ]);
                a[mf][2] = __float_as_uint(ar[(g    ) * KS + k0 + tg + 4]);
                a[mf][3] = __float_as_uint(ar[(g + 8) * KS + k0 + tg + 4]);
            }
#pragma unroll
            for (int nf = 0; nf < 8; nf++) {
                u32 b0 = __float_as_uint(bs[(nf * 8 + g) * KS + k0 + tg    ]);
                u32 b1 = __float_as_uint(bs[(nf * 8 + g) * KS + k0 + tg + 4]);
                mma8(c[0][nf], a[0], b0, b1);
                mma8(c[1][nf], a[1], b0, b1);
            }
        }
    }

    // epilogue
#pragma unroll
    for (int mf = 0; mf < 2; mf++) {
#pragma unroll
        for (int nf = 0; nf < 8; nf++) {
            const int r  = mbase + wm * 32 + mf * 16 + g;
            const int cl = nbase + wn * 64 + nf * 8 + 2 * tg;
            float* cc = c[mf][nf];
            if (EPI == 0) {
                const float b0 = bias[cl], b1 = bias[cl + 1];
                float2 o;
                o.x = __uint_as_float(f2tf(tanhf(cc[0] + b0)));
                o.y = __uint_as_float(f2tf(tanhf(cc[1] + b1)));
                *(float2*)(g_z + (u64)r * Da + cl) = o;
                o.x = __uint_as_float(f2tf(tanhf(cc[2] + b0)));
                o.y = __uint_as_float(f2tf(tanhf(cc[3] + b1)));
                *(float2*)(g_z + (u64)(r + 8) * Da + cl) = o;
            } else {
                if (cl < Sn) {
                    if (r < M2) {
                        float* dst = (r < Ln)
                            ? (dout + ((u64)bz * Ln + r) * Sn + cl)
                            : (g_w  + ((u64)bz * Ln + (r - Ln)) * Sn + cl);
                        *(float2*)dst = make_float2(cc[0], cc[1]);
                    }
                    const int r2 = r + 8;
                    if (r2 < M2) {
                        float* dst = (r2 < Ln)
                            ? (dout + ((u64)bz * Ln + r2) * Sn + cl)
                            : (g_w  + ((u64)bz * Ln + (r2 - Ln)) * Sn + cl);
                        *(float2*)dst = make_float2(cc[2], cc[3]);
                    }
                }
            }
        }
    }
}

// ---- block reduction (256 threads, 8 warps) ----
__device__ __forceinline__ float bred(float v, float* red, bool sum) {
#pragma unroll
    for (int o = 16; o; o >>= 1) {
        float t = __shfl_xor_sync(0xffffffffu, v, o);
        v = sum ? (v + t) : fmaxf(v, t);
    }
    __syncthreads();  // protect red[] from a previous use
    if ((threadIdx.x & 31) == 0) red[threadIdx.x >> 5] = v;
    __syncthreads();
    float out = red[0];
#pragma unroll
    for (int i = 1; i < 8; i++) out = sum ? (out + red[i]) : fmaxf(out, red[i]);
    return out;
}

// ---- finalize: softmax over each (b,l) row (in place in d_out) + y ----
__global__ void __launch_bounds__(256)
finalize_k(float* __restrict__ dout, const float* __restrict__ Vb) {
    const int bid = blockIdx.x;
    const int b = bid / Ln;
    const int l = bid - b * Ln;
    float*       arow = dout + (u64)Bn * Ln + ((u64)b * Ln + l) * Sn;  // scores in, alpha out
    const float* wrow = g_w  + ((u64)b * Ln + l) * Sn;
    const int tid = threadIdx.x;
    __shared__ float red[8];

    const int base = tid * 4;
    float4 r[4];
    float mx = -3.402823466e38f;
#pragma unroll
    for (int j = 0; j < 4; j++) {
        const int i = base + j * 1024;
        if (i < Sn) {
            r[j] = *(const float4*)(arow + i);
            mx = fmaxf(mx, fmaxf(fmaxf(r[j].x, r[j].y), fmaxf(r[j].z, r[j].w)));
        }
    }
    mx = bred(mx, red, false);

    float s = 0.f;
#pragma unroll
    for (int j = 0; j < 4; j++) {
        const int i = base + j * 1024;
        if (i < Sn) {
            r[j].x = __expf(r[j].x - mx);
            r[j].y = __expf(r[j].y - mx);
            r[j].z = __expf(r[j].z - mx);
            r[j].w = __expf(r[j].w - mx);
            s += r[j].x + r[j].y + r[j].z + r[j].w;
        }
    }
    s = bred(s, red, true);
    const float inv = 1.f / s;

    float y = 0.f;
#pragma unroll
    for (int j = 0; j < 4; j++) {
        const int i = base + j * 1024;
        if (i < Sn) {
            float4 w4 = *(const float4*)(wrow + i);
            float4 a4;
            a4.x = r[j].x * inv; a4.y = r[j].y * inv;
            a4.z = r[j].z * inv; a4.w = r[j].w * inv;
            *(float4*)(arow + i) = a4;
            y += a4.x * w4.x + a4.y * w4.y + a4.z * w4.z + a4.w * w4.w;
        }
    }
    y = bred(y, red, true);
    if (tid == 0) dout[(u64)b * Ln + l] = y + Vb[l];
}

// ---- launch ----
extern "C" void kernel_launch(void* const* d_in, const int* in_sizes, int n_in,
                              void* d_out, int out_size) {
    const float* x  = (const float*)d_in[0];
    const float* Ww = (const float*)d_in[1];
    const float* Wb = (const float*)d_in[2];
    const float* Uw = (const float*)d_in[3];
    const float* Vw = (const float*)d_in[4];
    const float* Vb = (const float*)d_in[5];
    float* out = (float*)d_out;

    cudaFuncSetAttribute(gemm_k<0>, cudaFuncAttributeMaxDynamicSharedMemorySize, (int)SMEM_BYTES);
    cudaFuncSetAttribute(gemm_k<1>, cudaFuncAttributeMaxDynamicSharedMemorySize, (int)SMEM_BYTES);

    // round inputs to tf32 (float4 element counts)
    round_k<<<(4096000 + 255) / 256, 256>>>(x,  4096000, 0);
    round_k<<<( 131072 + 255) / 256, 256>>>(Ww,  131072, 1);
    round_k<<<(1141888 + 255) / 256, 256>>>(Uw, 1141888, 2);
    round_k<<<(1141888 + 255) / 256, 256>>>(Vw, 1141888, 3);

    // z = tanh(x W^T + b)
    gemm_k<0><<<dim3(4, 125, 1), 256, SMEM_BYTES>>>(Wb, nullptr);
    // [scores; w] = [U; V] z^T  (scores -> d_out alpha region, w -> g_w)
    gemm_k<1><<<dim3(32, 140, 4), 256, SMEM_BYTES>>>(nullptr, out + (u64)Bn * Ln);
    // softmax rows in place + y
    finalize_k<<<Bn * Ln, 256>>>(out, Vb);
}

// round 11
// speedup vs baseline: 2.0449x; 1.5146x over previous
#include <cuda_runtime.h>
#include <cuda_fp16.h>

typedef unsigned int u32;
typedef unsigned long long u64;

static constexpr int Bn  = 4;
static constexpr int Sn  = 4000;
static constexpr int Din = 1024;
static constexpr int Da  = 512;
static constexpr int Ln  = 8921;
static constexpr int M2  = 2 * Ln;       // 17842 rows: [U; V]
static constexpr int M2pad = 17920;      // 140 * 128
static constexpr int Zrows = Bn * Sn;    // 16000
static constexpr int Zpad  = Zrows + 128;

// ---- scratch (device globals; zero-initialized; no allocation allowed) ----
__device__ __half g_xh [(u64)Bn * Sn * Din];   // x -> fp16
__device__ __half g_wh [(u64)Da * Din];        // W_w -> fp16
__device__ __half g_uvh[(u64)M2pad * Da];      // [U; V] -> fp16 (pad rows zero)
__device__ __half g_zh [(u64)Zpad * Da];       // z = tanh(xW^T+b) -> fp16 (pad zero)
__device__ float  g_w  [(u64)Bn * Ln * Sn];    // w = V z^T (571 MB)

// single dynamic-shared declaration shared by all kernels
extern __shared__ __align__(1024) char dyn_smem[];

// ---- helpers ----
__device__ __forceinline__ void cp16(u32 saddr, const void* g) {
    asm volatile("cp.async.cg.shared.global [%0], [%1], 16;\n" :: "r"(saddr), "l"(g));
}

__device__ __forceinline__ void mma16(float* c, u32 a0, u32 a1, u32 a2, u32 a3,
                                      u32 b0, u32 b1) {
    asm volatile(
        "mma.sync.aligned.m16n8k16.row.col.f32.f16.f16.f32 "
        "{%0,%1,%2,%3}, {%4,%5,%6,%7}, {%8,%9}, {%0,%1,%2,%3};\n"
        : "+f"(c[0]), "+f"(c[1]), "+f"(c[2]), "+f"(c[3])
        : "r"(a0), "r"(a1), "r"(a2), "r"(a3), "r"(b0), "r"(b1));
}

// ---- input conversion fp32 -> fp16 ----
// Each thread converts one float4 -> 4 halves (8B store).
__global__ void round_k(const float* __restrict__ in, int n4, int sel) {
    int i = blockIdx.x * blockDim.x + threadIdx.x;
    if (i >= n4) return;
    __half* out = (sel == 0) ? g_xh
                : (sel == 1) ? g_wh
                : (sel == 2) ? g_uvh
                             : (g_uvh + (u64)Ln * Da);
    float4 v = ((const float4*)in)[i];
    __half2 h0 = __floats2half2_rn(v.x, v.y);
    __half2 h1 = __floats2half2_rn(v.z, v.w);
    uint2 o;
    o.x = *(u32*)&h0;
    o.y = *(u32*)&h1;
    ((uint2*)out)[i] = o;
}

// ---- tiled fp16 GEMM: C[m,n] = sum_k A[m,k]*B[n,k]  (4-stage, 1 sync/iter) ----
// EPI==0: z-GEMM  (A=g_xh [16000,1024], B=g_wh [512,1024]) -> g_zh, tanh+bias
// EPI==1: sw-GEMM (A=g_uvh [17920,512], B=g_zh(batch) [4000+,512])
//         rows < Ln -> scores into d_out alpha region; rows >= Ln -> g_w
static constexpr int BM = 128, BN = 128, BK = 32;   // BK in halves (64 B)
static constexpr int ROWB = 80;                      // padded row pitch in bytes
static constexpr int STAGES = 4;
static constexpr u32 TILEB  = (u32)BM * ROWB;        // 10240 B per operand tile
static constexpr u32 STAGEB = 2u * TILEB;            // 20480 B (A + B)
static constexpr u32 SMEM_BYTES = STAGEB * STAGES;   // 81920 B

template<int EPI>
__global__ void __launch_bounds__(256, 2)
gemm_k(const float* __restrict__ bias, float* __restrict__ dout) {
    constexpr int K   = (EPI == 0) ? Din : Da;
    constexpr int KIT = K / BK;

    const u32 sb = (u32)__cvta_generic_to_shared(dyn_smem);
    const int tid   = threadIdx.x;
    const int nbase = blockIdx.x * BN;
    const int mbase = blockIdx.y * BM;
    const int bz    = blockIdx.z;

    const __half* Ag = (EPI == 0) ? g_xh : g_uvh;
    const __half* Bg = (EPI == 0) ? g_wh : (g_zh + (u64)bz * Sn * Da);

    // cp.async granules: tile = 128 rows x 4 x 16B = 512 granules per operand;
    // 256 threads -> 2 A granules + 2 B granules each
    u32 adst[2]; const __half* asrc[2];
    u32 bdst[2]; const __half* bsrc[2];
#pragma unroll
    for (int i = 0; i < 2; i++) {
        const int gi = tid + i * 256;           // 0..511
        const int r = gi >> 2, q = gi & 3;
        adst[i] = (u32)(r * ROWB + q * 16);
        bdst[i] = TILEB + (u32)(r * ROWB + q * 16);
        asrc[i] = Ag + (u64)(mbase + r) * K + q * 8;
        bsrc[i] = Bg + (u64)(nbase + r) * K + q * 8;
    }

    auto issue = [&](int kt, int st) {
        const u32 base = sb + (u32)st * STAGEB;
        const int ko = kt * BK;
#pragma unroll
        for (int i = 0; i < 2; i++) cp16(base + adst[i], asrc[i] + ko);
#pragma unroll
        for (int i = 0; i < 2; i++) cp16(base + bdst[i], bsrc[i] + ko);
        asm volatile("cp.async.commit_group;\n");
    };

    issue(0, 0); issue(1, 1); issue(2, 2);

    const int warp = tid >> 5, lane = tid & 31;
    const int g = lane >> 2, tg = lane & 3;
    const int wm = warp & 3, wn = warp >> 2;    // 4(M) x 2(N); warp tile 32x64

    float c[2][8][4];
#pragma unroll
    for (int mf = 0; mf < 2; mf++)
#pragma unroll
        for (int nf = 0; nf < 8; nf++)
#pragma unroll
            for (int i = 0; i < 4; i++) c[mf][nf][i] = 0.f;

    const char* smem = dyn_smem;

    for (int kt = 0; kt < KIT; kt++) {
        const int st = kt % STAGES;
        if      (kt <  KIT - 2) asm volatile("cp.async.wait_group 2;\n");
        else if (kt == KIT - 2) asm volatile("cp.async.wait_group 1;\n");
        else                    asm volatile("cp.async.wait_group 0;\n");
        __syncthreads();

        if (kt + 3 < KIT) issue(kt + 3, (kt + 3) % STAGES);

        const char* as = smem + (u32)st * STAGEB + (wm * 32 + g) * ROWB;
        const char* bs = smem + (u32)st * STAGEB + TILEB + (wn * 64 + g) * ROWB;
#pragma unroll
        for (int ks = 0; ks < 2; ks++) {            // two k16 steps per BK=32
            const int kb = ks * 32 + 4 * tg;        // byte offset of k-pair
            u32 a[2][4];
#pragma unroll
            for (int mf = 0; mf < 2; mf++) {
                const char* ar = as + (mf * 16) * ROWB;
                a[mf][0] = *(const u32*)(ar + kb);                // {g,   2tg..}
                a[mf][1] = *(const u32*)(ar + 8 * ROWB + kb);     // {g+8, 2tg..}
                a[mf][2] = *(const u32*)(ar + kb + 16);           // {g,   2tg+8..}
                a[mf][3] = *(const u32*)(ar + 8 * ROWB + kb + 16);
            }
#pragma unroll
            for (int nf = 0; nf < 8; nf++) {
                const char* br = bs + (nf * 8) * ROWB;
                u32 b0 = *(const u32*)(br + kb);
                u32 b1 = *(const u32*)(br + kb + 16);
                mma16(c[0][nf], a[0][0], a[0][1], a[0][2], a[0][3], b0, b1);
                mma16(c[1][nf], a[1][0], a[1][1], a[1][2], a[1][3], b0, b1);
            }
        }
    }

    // epilogue
#pragma unroll
    for (int mf = 0; mf < 2; mf++) {
#pragma unroll
        for (int nf = 0; nf < 8; nf++) {
            const int r  = mbase + wm * 32 + mf * 16 + g;
            const int cl = nbase + wn * 64 + nf * 8 + 2 * tg;
            float* cc = c[mf][nf];
            if (EPI == 0) {
                const float b0 = bias[cl], b1 = bias[cl + 1];
                __half2 o;
                o = __floats2half2_rn(tanhf(cc[0] + b0), tanhf(cc[1] + b1));
                *(__half2*)(g_zh + (u64)r * Da + cl) = o;
                o = __floats2half2_rn(tanhf(cc[2] + b0), tanhf(cc[3] + b1));
                *(__half2*)(g_zh + (u64)(r + 8) * Da + cl) = o;
            } else {
                if (cl < Sn) {
                    if (r < M2) {
                        float* dst = (r < Ln)
                            ? (dout + ((u64)bz * Ln + r) * Sn + cl)
                            : (g_w  + ((u64)bz * Ln + (r - Ln)) * Sn + cl);
                        *(float2*)dst = make_float2(cc[0], cc[1]);
                    }
                    const int r2 = r + 8;
                    if (r2 < M2) {
                        float* dst = (r2 < Ln)
                            ? (dout + ((u64)bz * Ln + r2) * Sn + cl)
                            : (g_w  + ((u64)bz * Ln + (r2 - Ln)) * Sn + cl);
                        *(float2*)dst = make_float2(cc[2], cc[3]);
                    }
                }
            }
        }
    }
}

// ---- block reduction (256 threads, 8 warps) ----
__device__ __forceinline__ float bred(float v, float* red, bool sum) {
#pragma unroll
    for (int o = 16; o; o >>= 1) {
        float t = __shfl_xor_sync(0xffffffffu, v, o);
        v = sum ? (v + t) : fmaxf(v, t);
    }
    __syncthreads();  // protect red[] from a previous use
    if ((threadIdx.x & 31) == 0) red[threadIdx.x >> 5] = v;
    __syncthreads();
    float out = red[0];
#pragma unroll
    for (int i = 1; i < 8; i++) out = sum ? (out + red[i]) : fmaxf(out, red[i]);
    return out;
}

// ---- finalize: softmax over each (b,l) row (in place in d_out) + y ----
__global__ void __launch_bounds__(256)
finalize_k(float* __restrict__ dout, const float* __restrict__ Vb) {
    const int bid = blockIdx.x;
    const int b = bid / Ln;
    const int l = bid - b * Ln;
    float*       arow = dout + (u64)Bn * Ln + ((u64)b * Ln + l) * Sn;  // scores in, alpha out
    const float* wrow = g_w  + ((u64)b * Ln + l) * Sn;
    const int tid = threadIdx.x;
    __shared__ float red[8];

    const int base = tid * 4;
    float4 r[4];
    float mx = -3.402823466e38f;
#pragma unroll
    for (int j = 0; j < 4; j++) {
        const int i = base + j * 1024;
        if (i < Sn) {
            r[j] = *(const float4*)(arow + i);
            mx = fmaxf(mx, fmaxf(fmaxf(r[j].x, r[j].y), fmaxf(r[j].z, r[j].w)));
        }
    }
    mx = bred(mx, red, false);

    float s = 0.f;
#pragma unroll
    for (int j = 0; j < 4; j++) {
        const int i = base + j * 1024;
        if (i < Sn) {
            r[j].x = __expf(r[j].x - mx);
            r[j].y = __expf(r[j].y - mx);
            r[j].z = __expf(r[j].z - mx);
            r[j].w = __expf(r[j].w - mx);
            s += r[j].x + r[j].y + r[j].z + r[j].w;
        }
    }
    s = bred(s, red, true);
    const float inv = 1.f / s;

    float y = 0.f;
#pragma unroll
    for (int j = 0; j < 4; j++) {
        const int i = base + j * 1024;
        if (i < Sn) {
            float4 w4 = *(const float4*)(wrow + i);
            float4 a4;
            a4.x = r[j].x * inv; a4.y = r[j].y * inv;
            a4.z = r[j].z * inv; a4.w = r[j].w * inv;
            *(float4*)(arow + i) = a4;
            y += a4.x * w4.x + a4.y * w4.y + a4.z * w4.z + a4.w * w4.w;
        }
    }
    y = bred(y, red, true);
    if (tid == 0) dout[(u64)b * Ln + l] = y + Vb[l];
}

// ---- launch ----
extern "C" void kernel_launch(void* const* d_in, const int* in_sizes, int n_in,
                              void* d_out, int out_size) {
    const float* x  = (const float*)d_in[0];
    const float* Ww = (const float*)d_in[1];
    const float* Wb = (const float*)d_in[2];
    const float* Uw = (const float*)d_in[3];
    const float* Vw = (const float*)d_in[4];
    const float* Vb = (const float*)d_in[5];
    float* out = (float*)d_out;

    cudaFuncSetAttribute(gemm_k<0>, cudaFuncAttributeMaxDynamicSharedMemorySize, (int)SMEM_BYTES);
    cudaFuncSetAttribute(gemm_k<1>, cudaFuncAttributeMaxDynamicSharedMemorySize, (int)SMEM_BYTES);

    // convert inputs to fp16 (float4 element counts)
    round_k<<<(4096000 + 255) / 256, 256>>>(x,  4096000, 0);
    round_k<<<( 131072 + 255) / 256, 256>>>(Ww,  131072, 1);
    round_k<<<(1141888 + 255) / 256, 256>>>(Uw, 1141888, 2);
    round_k<<<(1141888 + 255) / 256, 256>>>(Vw, 1141888, 3);

    // z = tanh(x W^T + b) -> g_zh
    gemm_k<0><<<dim3(4, 125, 1), 256, SMEM_BYTES>>>(Wb, nullptr);
    // [scores; w] = [U; V] z^T  (scores -> d_out alpha region, w -> g_w)
    gemm_k<1><<<dim3(32, 140, 4), 256, SMEM_BYTES>>>(nullptr, out + (u64)Bn * Ln);
    // softmax rows in place + y
    finalize_k<<<Bn * Ln, 256>>>(out, Vb);
}

// round 13
// speedup vs baseline: 2.1253x; 1.0393x over previous
#include <cuda_runtime.h>
#include <cuda_fp16.h>

typedef unsigned int u32;
typedef unsigned long long u64;

static constexpr int Bn  = 4;
static constexpr int Sn  = 4000;
static constexpr int Din = 1024;
static constexpr int Da  = 512;
static constexpr int Ln  = 8921;
static constexpr int M2  = 2 * Ln;       // 17842 rows: [U; V]
static constexpr int M2pad = 17920;      // 140 * 128
static constexpr int Zrows = Bn * Sn;    // 16000
static constexpr int Zpad  = Zrows + 128;

// ---- scratch (device globals; zero-initialized; no allocation allowed) ----
__device__ __half g_xh [(u64)Bn * Sn * Din];   // x -> fp16
__device__ __half g_wh [(u64)Da * Din];        // W_w -> fp16
__device__ __half g_uvh[(u64)M2pad * Da];      // [U; V] -> fp16 (pad rows zero)
__device__ __half g_zh [(u64)Zpad * Da];       // z = tanh(xW^T+b) -> fp16 (pad zero)
__device__ __half g_w  [(u64)Bn * Ln * Sn];    // w = V z^T (286 MB, fp16)

// single dynamic-shared declaration shared by all kernels
extern __shared__ __align__(1024) char dyn_smem[];

// ---- helpers ----
__device__ __forceinline__ void cp16(u32 saddr, const void* g) {
    asm volatile("cp.async.cg.shared.global [%0], [%1], 16;\n" :: "r"(saddr), "l"(g));
}

__device__ __forceinline__ void mma16(float* c, u32 a0, u32 a1, u32 a2, u32 a3,
                                      u32 b0, u32 b1) {
    asm volatile(
        "mma.sync.aligned.m16n8k16.row.col.f32.f16.f16.f32 "
        "{%0,%1,%2,%3}, {%4,%5,%6,%7}, {%8,%9}, {%0,%1,%2,%3};\n"
        : "+f"(c[0]), "+f"(c[1]), "+f"(c[2]), "+f"(c[3])
        : "r"(a0), "r"(a1), "r"(a2), "r"(a3), "r"(b0), "r"(b1));
}

// ---- input conversion fp32 -> fp16 ----
__global__ void round_k(const float* __restrict__ in, int n4, int sel) {
    int i = blockIdx.x * blockDim.x + threadIdx.x;
    if (i >= n4) return;
    __half* out = (sel == 0) ? g_xh
                : (sel == 1) ? g_wh
                : (sel == 2) ? g_uvh
                             : (g_uvh + (u64)Ln * Da);
    float4 v = ((const float4*)in)[i];
    __half2 h0 = __floats2half2_rn(v.x, v.y);
    __half2 h1 = __floats2half2_rn(v.z, v.w);
    uint2 o;
    o.x = *(u32*)&h0;
    o.y = *(u32*)&h1;
    ((uint2*)out)[i] = o;
}

// ---- tiled fp16 GEMM: C[m,n] = sum_k A[m,k]*B[n,k]  (4-stage, 1 sync/iter) ----
// EPI==0: z-GEMM  (A=g_xh [16000,1024], B=g_wh [512,1024]) -> g_zh, tanh+bias
// EPI==1: sw-GEMM (A=g_uvh [17920,512], B=g_zh(batch) [4000+,512])
//         rows < Ln -> scores (fp32) into d_out alpha region; rows >= Ln -> g_w (fp16)
static constexpr int BM = 128, BN = 128, BK = 32;   // BK in halves (64 B)
static constexpr int ROWB = 80;                      // padded row pitch in bytes
static constexpr int STAGES = 4;
static constexpr u32 TILEB  = (u32)BM * ROWB;        // 10240 B per operand tile
static constexpr u32 STAGEB = 2u * TILEB;            // 20480 B (A + B)
static constexpr u32 SMEM_BYTES = STAGEB * STAGES;   // 81920 B

template<int EPI>
__global__ void __launch_bounds__(256, 2)
gemm_k(const float* __restrict__ bias, float* __restrict__ dout) {
    constexpr int K   = (EPI == 0) ? Din : Da;
    constexpr int KIT = K / BK;

    const u32 sb = (u32)__cvta_generic_to_shared(dyn_smem);
    const int tid   = threadIdx.x;
    const int nbase = blockIdx.x * BN;
    const int mbase = blockIdx.y * BM;
    const int bz    = blockIdx.z;

    const __half* Ag = (EPI == 0) ? g_xh : g_uvh;
    const __half* Bg = (EPI == 0) ? g_wh : (g_zh + (u64)bz * Sn * Da);

    // cp.async granules: tile = 128 rows x 4 x 16B = 512 granules per operand;
    // 256 threads -> 2 A granules + 2 B granules each
    u32 adst[2]; const __half* asrc[2];
    u32 bdst[2]; const __half* bsrc[2];
#pragma unroll
    for (int i = 0; i < 2; i++) {
        const int gi = tid + i * 256;           // 0..511
        const int r = gi >> 2, q = gi & 3;
        adst[i] = (u32)(r * ROWB + q * 16);
        bdst[i] = TILEB + (u32)(r * ROWB + q * 16);
        asrc[i] = Ag + (u64)(mbase + r) * K + q * 8;
        bsrc[i] = Bg + (u64)(nbase + r) * K + q * 8;
    }

    auto issue = [&](int kt, int st) {
        const u32 base = sb + (u32)st * STAGEB;
        const int ko = kt * BK;
#pragma unroll
        for (int i = 0; i < 2; i++) cp16(base + adst[i], asrc[i] + ko);
#pragma unroll
        for (int i = 0; i < 2; i++) cp16(base + bdst[i], bsrc[i] + ko);
        asm volatile("cp.async.commit_group;\n");
    };

    issue(0, 0); issue(1, 1); issue(2, 2);

    const int warp = tid >> 5, lane = tid & 31;
    const int g = lane >> 2, tg = lane & 3;
    const int wm = warp & 3, wn = warp >> 2;    // 4(M) x 2(N); warp tile 32x64

    float c[2][8][4];
#pragma unroll
    for (int mf = 0; mf < 2; mf++)
#pragma unroll
        for (int nf = 0; nf < 8; nf++)
#pragma unroll
            for (int i = 0; i < 4; i++) c[mf][nf][i] = 0.f;

    const char* smem = dyn_smem;

    for (int kt = 0; kt < KIT; kt++) {
        const int st = kt % STAGES;
        if      (kt <  KIT - 2) asm volatile("cp.async.wait_group 2;\n");
        else if (kt == KIT - 2) asm volatile("cp.async.wait_group 1;\n");
        else                    asm volatile("cp.async.wait_group 0;\n");
        __syncthreads();

        if (kt + 3 < KIT) issue(kt + 3, (kt + 3) % STAGES);

        const char* as = smem + (u32)st * STAGEB + (wm * 32 + g) * ROWB;
        const char* bs = smem + (u32)st * STAGEB + TILEB + (wn * 64 + g) * ROWB;
#pragma unroll
        for (int ks = 0; ks < 2; ks++) {            // two k16 steps per BK=32
            const int kb = ks * 32 + 4 * tg;        // byte offset of k-pair
            u32 a[2][4];
#pragma unroll
            for (int mf = 0; mf < 2; mf++) {
                const char* ar = as + (mf * 16) * ROWB;
                a[mf][0] = *(const u32*)(ar + kb);                // {g,   2tg..}
                a[mf][1] = *(const u32*)(ar + 8 * ROWB + kb);     // {g+8, 2tg..}
                a[mf][2] = *(const u32*)(ar + kb + 16);           // {g,   2tg+8..}
                a[mf][3] = *(const u32*)(ar + 8 * ROWB + kb + 16);
            }
#pragma unroll
            for (int nf = 0; nf < 8; nf++) {
                const char* br = bs + (nf * 8) * ROWB;
                u32 b0 = *(const u32*)(br + kb);
                u32 b1 = *(const u32*)(br + kb + 16);
                mma16(c[0][nf], a[0][0], a[0][1], a[0][2], a[0][3], b0, b1);
                mma16(c[1][nf], a[1][0], a[1][1], a[1][2], a[1][3], b0, b1);
            }
        }
    }

    // epilogue
#pragma unroll
    for (int mf = 0; mf < 2; mf++) {
#pragma unroll
        for (int nf = 0; nf < 8; nf++) {
            const int r  = mbase + wm * 32 + mf * 16 + g;
            const int cl = nbase + wn * 64 + nf * 8 + 2 * tg;
            float* cc = c[mf][nf];
            if (EPI == 0) {
                const float b0 = bias[cl], b1 = bias[cl + 1];
                __half2 o;
                o = __floats2half2_rn(tanhf(cc[0] + b0), tanhf(cc[1] + b1));
                *(__half2*)(g_zh + (u64)r * Da + cl) = o;
                o = __floats2half2_rn(tanhf(cc[2] + b0), tanhf(cc[3] + b1));
                *(__half2*)(g_zh + (u64)(r + 8) * Da + cl) = o;
            } else {
                if (cl < Sn) {
#pragma unroll
                    for (int rr = 0; rr < 2; rr++) {
                        const int row = r + rr * 8;
                        if (row >= M2) continue;
                        if (row < Ln) {
                            float* dst = dout + ((u64)bz * Ln + row) * Sn + cl;
                            *(float2*)dst = make_float2(cc[rr * 2 + 0], cc[rr * 2 + 1]);
                        } else {
                            __half* dst = g_w + ((u64)bz * Ln + (row - Ln)) * Sn + cl;
                            *(__half2*)dst = __floats2half2_rn(cc[rr * 2 + 0], cc[rr * 2 + 1]);
                        }
                    }
                }
            }
        }
    }
}

// ---- block reduction (256 threads, 8 warps) ----
__device__ __forceinline__ float bred(float v, float* red, bool sum) {
#pragma unroll
    for (int o = 16; o; o >>= 1) {
        float t = __shfl_xor_sync(0xffffffffu, v, o);
        v = sum ? (v + t) : fmaxf(v, t);
    }
    __syncthreads();  // protect red[] from a previous use
    if ((threadIdx.x & 31) == 0) red[threadIdx.x >> 5] = v;
    __syncthreads();
    float out = red[0];
#pragma unroll
    for (int i = 1; i < 8; i++) out = sum ? (out + red[i]) : fmaxf(out, red[i]);
    return out;
}

// ---- finalize: softmax over each (b,l) row (in place in d_out) + y ----
__global__ void __launch_bounds__(256)
finalize_k(float* __restrict__ dout, const float* __restrict__ Vb) {
    const int bid = blockIdx.x;
    const int b = bid / Ln;
    const int l = bid - b * Ln;
    float*        arow = dout + (u64)Bn * Ln + ((u64)b * Ln + l) * Sn;  // scores in, alpha out
    const __half* wrow = g_w  + ((u64)b * Ln + l) * Sn;
    const int tid = threadIdx.x;
    __shared__ float red[8];

    const int base = tid * 4;
    float4 r[4];
    float mx = -3.402823466e38f;
#pragma unroll
    for (int j = 0; j < 4; j++) {
        const int i = base + j * 1024;
        if (i < Sn) {
            r[j] = *(const float4*)(arow + i);
            mx = fmaxf(mx, fmaxf(fmaxf(r[j].x, r[j].y), fmaxf(r[j].z, r[j].w)));
        }
    }
    mx = bred(mx, red, false);

    float s = 0.f;
#pragma unroll
    for (int j = 0; j < 4; j++) {
        const int i = base + j * 1024;
        if (i < Sn) {
            r[j].x = __expf(r[j].x - mx);
            r[j].y = __expf(r[j].y - mx);
            r[j].z = __expf(r[j].z - mx);
            r[j].w = __expf(r[j].w - mx);
            s += r[j].x + r[j].y + r[j].z + r[j].w;
        }
    }
    s = bred(s, red, true);
    const float inv = 1.f / s;

    float y = 0.f;
#pragma unroll
    for (int j = 0; j < 4; j++) {
        const int i = base + j * 1024;
        if (i < Sn) {
            // 4 halves = 8B load
            uint2 wq = *(const uint2*)(wrow + i);
            float2 w0 = __half22float2(*(__half2*)&wq.x);
            float2 w1 = __half22float2(*(__half2*)&wq.y);
            float4 a4;
            a4.x = r[j].x * inv; a4.y = r[j].y * inv;
            a4.z = r[j].z * inv; a4.w = r[j].w * inv;
            *(float4*)(arow + i) = a4;
            y += a4.x * w0.x + a4.y * w0.y + a4.z * w1.x + a4.w * w1.y;
        }
    }
    y = bred(y, red, true);
    if (tid == 0) dout[(u64)b * Ln + l] = y + Vb[l];
}

// ---- launch ----
extern "C" void kernel_launch(void* const* d_in, const int* in_sizes, int n_in,
                              void* d_out, int out_size) {
    const float* x  = (const float*)d_in[0];
    const float* Ww = (const float*)d_in[1];
    const float* Wb = (const float*)d_in[2];
    const float* Uw = (const float*)d_in[3];
    const float* Vw = (const float*)d_in[4];
    const float* Vb = (const float*)d_in[5];
    float* out = (float*)d_out;

    cudaFuncSetAttribute(gemm_k<0>, cudaFuncAttributeMaxDynamicSharedMemorySize, (int)SMEM_BYTES);
    cudaFuncSetAttribute(gemm_k<1>, cudaFuncAttributeMaxDynamicSharedMemorySize, (int)SMEM_BYTES);

    // convert inputs to fp16 (float4 element counts)
    round_k<<<(4096000 + 255) / 256, 256>>>(x,  4096000, 0);
    round_k<<<( 131072 + 255) / 256, 256>>>(Ww,  131072, 1);
    round_k<<<(1141888 + 255) / 256, 256>>>(Uw, 1141888, 2);
    round_k<<<(1141888 + 255) / 256, 256>>>(Vw, 1141888, 3);

    // z = tanh(x W^T + b) -> g_zh
    gemm_k<0><<<dim3(4, 125, 1), 256, SMEM_BYTES>>>(Wb, nullptr);
    // [scores; w] = [U; V] z^T  (scores -> d_out alpha region, w -> g_w fp16)
    gemm_k<1><<<dim3(32, 140, 4), 256, SMEM_BYTES>>>(nullptr, out + (u64)Bn * Ln);
    // softmax rows in place + y
    finalize_k<<<Bn * Ln, 256>>>(out, Vb);
}

// round 15
// speedup vs baseline: 2.2554x; 1.0612x over previous
#include <cuda_runtime.h>
#include <cuda_fp16.h>

typedef unsigned int u32;
typedef unsigned long long u64;

static constexpr int Bn  = 4;
static constexpr int Sn  = 4000;
static constexpr int Din = 1024;
static constexpr int Da  = 512;
static constexpr int Ln  = 8921;
static constexpr int M2pad = 17920;      // 140 * 128 rows (U/V interleaved by 8)
static constexpr int Zrows = Bn * Sn;    // 16000
static constexpr int Zpad  = Zrows + 128;

// ---- scratch (device globals; zero-initialized; no allocation allowed) ----
__device__ __half g_xh [(u64)Bn * Sn * Din];   // x -> fp16
__device__ __half g_wh [(u64)Da * Din];        // W_w -> fp16
__device__ __half g_uvh[(u64)M2pad * Da];      // U/V fp16, label i: U@16(i/8)+i%8, V@+8
__device__ __half g_zh [(u64)Zpad * Da];       // z = tanh(xW^T+b) -> fp16 (pad zero)
__device__ float  g_sum [(u64)Bn * Ln];        // per (b,l): sum of exp(score)
__device__ float  g_ynum[(u64)Bn * Ln];        // per (b,l): sum of exp(score)*w

// single dynamic-shared declaration shared by all kernels
extern __shared__ __align__(1024) char dyn_smem[];

// ---- helpers ----
__device__ __forceinline__ void cp16(u32 saddr, const void* g) {
    asm volatile("cp.async.cg.shared.global [%0], [%1], 16;\n" :: "r"(saddr), "l"(g));
}

__device__ __forceinline__ void mma16(float* c, u32 a0, u32 a1, u32 a2, u32 a3,
                                      u32 b0, u32 b1) {
    asm volatile(
        "mma.sync.aligned.m16n8k16.row.col.f32.f16.f16.f32 "
        "{%0,%1,%2,%3}, {%4,%5,%6,%7}, {%8,%9}, {%0,%1,%2,%3};\n"
        : "+f"(c[0]), "+f"(c[1]), "+f"(c[2]), "+f"(c[3])
        : "r"(a0), "r"(a1), "r"(a2), "r"(a3), "r"(b0), "r"(b1));
}

// ---- zero accumulators (must run before gemm2 on every replay) ----
__global__ void zero_k() {
    const int i = blockIdx.x * blockDim.x + threadIdx.x;
    if (i < Bn * Ln) { g_sum[i] = 0.f; g_ynum[i] = 0.f; }
}

// ---- input conversion fp32 -> fp16 ----
// sel 0: x, sel 1: W, sel 2: U (interleaved rows), sel 3: V (interleaved rows)
__global__ void round_k(const float* __restrict__ in, int n4, int sel) {
    int i = blockIdx.x * blockDim.x + threadIdx.x;
    if (i >= n4) return;
    float4 v = ((const float4*)in)[i];
    __half2 h0 = __floats2half2_rn(v.x, v.y);
    __half2 h1 = __floats2half2_rn(v.z, v.w);
    uint2 o;
    o.x = *(u32*)&h0;
    o.y = *(u32*)&h1;
    if (sel <= 1) {
        __half* out = (sel == 0) ? g_xh : g_wh;
        ((uint2*)out)[i] = o;
    } else {
        const int f = i * 4;
        const int r = f >> 9;              // label index (Da = 512)
        const int k = f & 511;
        const int R = ((r >> 3) << 4) + (r & 7) + ((sel == 3) ? 8 : 0);
        *(uint2*)(g_uvh + (u64)R * Da + k) = o;
    }
}

// ---- tiled fp16 GEMM (4-stage, 1 sync/iter) ----
// EPI==0: z-GEMM  (A=g_xh [16000,1024], B=g_wh [512,1024]) -> g_zh, tanh+bias
// EPI==1: sw-GEMM (A=g_uvh interleaved [17920,512], B=g_zh(batch) [4000+,512])
//         epilogue: e=exp(score)->alpha region (unnormalized); atomic sum / y-num
static constexpr int BM = 128, BN = 128, BK = 32;   // BK in halves (64 B)
static constexpr int ROWB = 80;                      // padded row pitch in bytes
static constexpr int STAGES = 4;
static constexpr u32 TILEB  = (u32)BM * ROWB;        // 10240 B per operand tile
static constexpr u32 STAGEB = 2u * TILEB;            // 20480 B (A + B)
static constexpr u32 SMEM_BYTES = STAGEB * STAGES;   // 81920 B

template<int EPI>
__global__ void __launch_bounds__(256, 2)
gemm_k(const float* __restrict__ bias, float* __restrict__ dout) {
    constexpr int K   = (EPI == 0) ? Din : Da;
    constexpr int KIT = K / BK;

    const u32 sb = (u32)__cvta_generic_to_shared(dyn_smem);
    const int tid   = threadIdx.x;
    const int nbase = blockIdx.x * BN;
    const int mbase = blockIdx.y * BM;
    const int bz    = blockIdx.z;

    const __half* Ag = (EPI == 0) ? g_xh : g_uvh;
    const __half* Bg = (EPI == 0) ? g_wh : (g_zh + (u64)bz * Sn * Da);

    u32 adst[2]; const __half* asrc[2];
    u32 bdst[2]; const __half* bsrc[2];
#pragma unroll
    for (int i = 0; i < 2; i++) {
        const int gi = tid + i * 256;           // 0..511
        const int r = gi >> 2, q = gi & 3;
        adst[i] = (u32)(r * ROWB + q * 16);
        bdst[i] = TILEB + (u32)(r * ROWB + q * 16);
        asrc[i] = Ag + (u64)(mbase + r) * K + q * 8;
        bsrc[i] = Bg + (u64)(nbase + r) * K + q * 8;
    }

    auto issue = [&](int kt, int st) {
        const u32 base = sb + (u32)st * STAGEB;
        const int ko = kt * BK;
#pragma unroll
        for (int i = 0; i < 2; i++) cp16(base + adst[i], asrc[i] + ko);
#pragma unroll
        for (int i = 0; i < 2; i++) cp16(base + bdst[i], bsrc[i] + ko);
        asm volatile("cp.async.commit_group;\n");
    };

    issue(0, 0); issue(1, 1); issue(2, 2);

    const int warp = tid >> 5, lane = tid & 31;
    const int g = lane >> 2, tg = lane & 3;
    const int wm = warp & 3, wn = warp >> 2;    // 4(M) x 2(N); warp tile 32x64

    float c[2][8][4];
#pragma unroll
    for (int mf = 0; mf < 2; mf++)
#pragma unroll
        for (int nf = 0; nf < 8; nf++)
#pragma unroll
            for (int i = 0; i < 4; i++) c[mf][nf][i] = 0.f;

    const char* smem = dyn_smem;

    for (int kt = 0; kt < KIT; kt++) {
        const int st = kt % STAGES;
        if      (kt <  KIT - 2) asm volatile("cp.async.wait_group 2;\n");
        else if (kt == KIT - 2) asm volatile("cp.async.wait_group 1;\n");
        else                    asm volatile("cp.async.wait_group 0;\n");
        __syncthreads();

        if (kt + 3 < KIT) issue(kt + 3, (kt + 3) % STAGES);

        const char* as = smem + (u32)st * STAGEB + (wm * 32 + g) * ROWB;
        const char* bs = smem + (u32)st * STAGEB + TILEB + (wn * 64 + g) * ROWB;
#pragma unroll
        for (int ks = 0; ks < 2; ks++) {            // two k16 steps per BK=32
            const int kb = ks * 32 + 4 * tg;        // byte offset of k-pair
            u32 a[2][4];
#pragma unroll
            for (int mf = 0; mf < 2; mf++) {
                const char* ar = as + (mf * 16) * ROWB;
                a[mf][0] = *(const u32*)(ar + kb);
                a[mf][1] = *(const u32*)(ar + 8 * ROWB + kb);
                a[mf][2] = *(const u32*)(ar + kb + 16);
                a[mf][3] = *(const u32*)(ar + 8 * ROWB + kb + 16);
            }
#pragma unroll
            for (int nf = 0; nf < 8; nf++) {
                const char* br = bs + (nf * 8) * ROWB;
                u32 b0 = *(const u32*)(br + kb);
                u32 b1 = *(const u32*)(br + kb + 16);
                mma16(c[0][nf], a[0][0], a[0][1], a[0][2], a[0][3], b0, b1);
                mma16(c[1][nf], a[1][0], a[1][1], a[1][2], a[1][3], b0, b1);
            }
        }
    }

    // epilogue
#pragma unroll
    for (int mf = 0; mf < 2; mf++) {
        if (EPI == 0) {
#pragma unroll
            for (int nf = 0; nf < 8; nf++) {
                const int r  = mbase + wm * 32 + mf * 16 + g;
                const int cl = nbase + wn * 64 + nf * 8 + 2 * tg;
                float* cc = c[mf][nf];
                const float b0 = bias[cl], b1 = bias[cl + 1];
                __half2 o;
                o = __floats2half2_rn(tanhf(cc[0] + b0), tanhf(cc[1] + b1));
                *(__half2*)(g_zh + (u64)r * Da + cl) = o;
                o = __floats2half2_rn(tanhf(cc[2] + b0), tanhf(cc[3] + b1));
                *(__half2*)(g_zh + (u64)(r + 8) * Da + cl) = o;
            }
        } else {
            // cc[0..1]: score(label, cl..cl+1); cc[2..3]: w(label, cl..cl+1)
            const int row_u = mbase + wm * 32 + mf * 16 + g;      // row_u & 15 == g
            const int label = ((row_u >> 4) << 3) + g;
            const bool ok = (label < Ln);
            float sum_part = 0.f, y_part = 0.f;
#pragma unroll
            for (int nf = 0; nf < 8; nf++) {
                const int cl = nbase + wn * 64 + nf * 8 + 2 * tg;
                float* cc = c[mf][nf];
                if (ok && cl < Sn) {
                    const float e0 = __expf(cc[0]);
                    const float e1 = __expf(cc[1]);
                    *(float2*)(dout + ((u64)bz * Ln + label) * Sn + cl) =
                        make_float2(e0, e1);
                    sum_part += e0 + e1;
                    y_part   += e0 * cc[2] + e1 * cc[3];
                }
            }
            // reduce over the 4 tg-lanes sharing this label
            sum_part += __shfl_xor_sync(0xffffffffu, sum_part, 1);
            sum_part += __shfl_xor_sync(0xffffffffu, sum_part, 2);
            y_part   += __shfl_xor_sync(0xffffffffu, y_part, 1);
            y_part   += __shfl_xor_sync(0xffffffffu, y_part, 2);
            if (ok && tg == 0) {
                atomicAdd(g_sum  + (u64)bz * Ln + label, sum_part);
                atomicAdd(g_ynum + (u64)bz * Ln + label, y_part);
            }
        }
    }
}

// ---- finalize: scale unnormalized alpha in place; emit y ----
__global__ void __launch_bounds__(256)
finalize_k(float* __restrict__ dout, const float* __restrict__ Vb) {
    const int bid = blockIdx.x;
    const int b = bid / Ln;
    const int l = bid - b * Ln;
    float* arow = dout + (u64)Bn * Ln + ((u64)b * Ln + l) * Sn;
    const int tid = threadIdx.x;

    const float inv = 1.f / g_sum[(u64)b * Ln + l];
    if (tid == 0)
        dout[(u64)b * Ln + l] = g_ynum[(u64)b * Ln + l] * inv + Vb[l];

    const int base = tid * 4;
#pragma unroll
    for (int j = 0; j < 4; j++) {
        const int i = base + j * 1024;
        if (i < Sn) {
            float4 v = *(const float4*)(arow + i);
            v.x *= inv; v.y *= inv; v.z *= inv; v.w *= inv;
            *(float4*)(arow + i) = v;
        }
    }
}

// ---- launch ----
extern "C" void kernel_launch(void* const* d_in, const int* in_sizes, int n_in,
                              void* d_out, int out_size) {
    const float* x  = (const float*)d_in[0];
    const float* Ww = (const float*)d_in[1];
    const float* Wb = (const float*)d_in[2];
    const float* Uw = (const float*)d_in[3];
    const float* Vw = (const float*)d_in[4];
    const float* Vb = (const float*)d_in[5];
    float* out = (float*)d_out;

    cudaFuncSetAttribute(gemm_k<0>, cudaFuncAttributeMaxDynamicSharedMemorySize, (int)SMEM_BYTES);
    cudaFuncSetAttribute(gemm_k<1>, cudaFuncAttributeMaxDynamicSharedMemorySize, (int)SMEM_BYTES);

    // zero atomic accumulators (graph-replay safe)
    zero_k<<<(Bn * Ln + 255) / 256, 256>>>();

    // convert inputs to fp16 (float4 element counts)
    round_k<<<(4096000 + 255) / 256, 256>>>(x,  4096000, 0);
    round_k<<<( 131072 + 255) / 256, 256>>>(Ww,  131072, 1);
    round_k<<<(1141888 + 255) / 256, 256>>>(Uw, 1141888, 2);
    round_k<<<(1141888 + 255) / 256, 256>>>(Vw, 1141888, 3);

    // z = tanh(x W^T + b) -> g_zh
    gemm_k<0><<<dim3(4, 125, 1), 256, SMEM_BYTES>>>(Wb, nullptr);
    // fused scores/w GEMM: exp(scores) -> alpha region; atomics -> g_sum/g_ynum
    gemm_k<1><<<dim3(32, 140, 4), 256, SMEM_BYTES>>>(nullptr, out + (u64)Bn * Ln);
    // normalize alpha in place + y
    finalize_k<<<Bn * Ln, 256>>>(out, Vb);
}

// round 16
// speedup vs baseline: 2.4531x; 1.0877x over previous
#include <cuda_runtime.h>
#include <cuda_fp16.h>

typedef unsigned int u32;
typedef unsigned long long u64;

static constexpr int Bn  = 4;
static constexpr int Sn  = 4000;
static constexpr int Din = 1024;
static constexpr int Da  = 512;
static constexpr int Ln  = 8921;
static constexpr int M2pad = 17920;      // 140 * 128 rows (U/V interleaved by 8)
static constexpr int Zrows = Bn * Sn;    // 16000
static constexpr int Zpad  = Zrows + 128;

// ---- scratch (device globals; zero-initialized; no allocation allowed) ----
__device__ __half g_xh [(u64)Bn * Sn * Din];   // x -> fp16
__device__ __half g_wh [(u64)Da * Din];        // W_w -> fp16
__device__ __half g_uvh[(u64)M2pad * Da];      // U/V fp16, label i: U@16(i/8)+i%8, V@+8
__device__ __half g_zh [(u64)Zpad * Da];       // z = tanh(xW^T+b) -> fp16 (pad zero)
__device__ float  g_sum [(u64)Bn * Ln];        // per (b,l): sum of exp(score)
__device__ float  g_ynum[(u64)Bn * Ln];        // per (b,l): sum of exp(score)*w

// single dynamic-shared declaration shared by all kernels
extern __shared__ __align__(1024) char dyn_smem[];

// ---- helpers ----
__device__ __forceinline__ void cp16(u32 saddr, const void* g) {
    asm volatile("cp.async.cg.shared.global [%0], [%1], 16;\n" :: "r"(saddr), "l"(g));
}

__device__ __forceinline__ void mma16(float* c, u32 a0, u32 a1, u32 a2, u32 a3,
                                      u32 b0, u32 b1) {
    asm volatile(
        "mma.sync.aligned.m16n8k16.row.col.f32.f16.f16.f32 "
        "{%0,%1,%2,%3}, {%4,%5,%6,%7}, {%8,%9}, {%0,%1,%2,%3};\n"
        : "+f"(c[0]), "+f"(c[1]), "+f"(c[2]), "+f"(c[3])
        : "r"(a0), "r"(a1), "r"(a2), "r"(a3), "r"(b0), "r"(b1));
}

// ---- input conversion fp32 -> fp16 ----
// sel 0: x, sel 1: W (+ zero accumulators), sel 2: U (interleaved), sel 3: V (interleaved)
__global__ void round_k(const float* __restrict__ in, int n4, int sel) {
    int i = blockIdx.x * blockDim.x + threadIdx.x;
    if (i >= n4) return;
    if (sel == 1 && i < Bn * Ln) { g_sum[i] = 0.f; g_ynum[i] = 0.f; }
    float4 v = ((const float4*)in)[i];
    __half2 h0 = __floats2half2_rn(v.x, v.y);
    __half2 h1 = __floats2half2_rn(v.z, v.w);
    uint2 o;
    o.x = *(u32*)&h0;
    o.y = *(u32*)&h1;
    if (sel <= 1) {
        __half* out = (sel == 0) ? g_xh : g_wh;
        ((uint2*)out)[i] = o;
    } else {
        const int f = i * 4;
        const int r = f >> 9;              // label index (Da = 512)
        const int k = f & 511;
        const int R = ((r >> 3) << 4) + (r & 7) + ((sel == 3) ? 8 : 0);
        *(uint2*)(g_uvh + (u64)R * Da + k) = o;
    }
}

// ---- tiled fp16 GEMM (4-stage, 1 sync/iter) ----
// EPI==0: z-GEMM  (A=g_xh [16000,1024], B=g_wh [512,1024]), BN=128 -> g_zh, tanh+bias
// EPI==1: sw-GEMM (A=g_uvh interleaved [17920,512], B=g_zh(batch) [4000,512]), BN=160
//         epilogue: e=exp(score)->alpha region (unnormalized); atomic sum / y-num
static constexpr int BM = 128, BK = 32;              // BK in halves (64 B)
static constexpr int ROWB = 80;                      // padded row pitch in bytes
static constexpr int STAGES = 4;
static constexpr u32 A_TILEB = (u32)BM * ROWB;       // 10240 B

template<int EPI> struct Cfg {
    static constexpr int BN   = (EPI == 0) ? 128 : 160;
    static constexpr int NF   = BN / 16;             // 8 or 10 (per N-warp: BN/2 cols)
    static constexpr u32 BT   = (u32)BN * ROWB;      // B tile bytes
    static constexpr u32 STG  = A_TILEB + BT;        // stage bytes
    static constexpr u32 SME  = STG * STAGES;
    static constexpr int GRAN = (BM + BN) * 4;       // 16B granules per stage
    static constexpr int SLOT = (GRAN + 255) / 256;  // 4 or 5
};

template<int EPI>
__global__ void __launch_bounds__(256, 2)
gemm_k(const float* __restrict__ bias, float* __restrict__ dout) {
    using C = Cfg<EPI>;
    constexpr int K   = (EPI == 0) ? Din : Da;
    constexpr int KIT = K / BK;

    const u32 sb = (u32)__cvta_generic_to_shared(dyn_smem);
    const int tid   = threadIdx.x;
    const int nbase = blockIdx.x * C::BN;
    const int mbase = blockIdx.y * BM;
    const int bz    = blockIdx.z;

    const __half* Ag = (EPI == 0) ? g_xh : g_uvh;
    const __half* Bg = (EPI == 0) ? g_wh : (g_zh + (u64)bz * Sn * Da);

    u32 dst[C::SLOT]; const __half* src[C::SLOT]; bool ok_s[C::SLOT];
#pragma unroll
    for (int i = 0; i < C::SLOT; i++) {
        const int gi = tid + i * 256;
        ok_s[i] = (gi < C::GRAN);
        const int g2 = ok_s[i] ? gi : 0;
        if (g2 < 4 * BM) {       // A granule
            const int r = g2 >> 2, q = g2 & 3;
            dst[i] = (u32)(r * ROWB + q * 16);
            src[i] = Ag + (u64)(mbase + r) * K + q * 8;
        } else {                 // B granule
            const int g3 = g2 - 4 * BM;
            const int r = g3 >> 2, q = g3 & 3;
            dst[i] = A_TILEB + (u32)(r * ROWB + q * 16);
            src[i] = Bg + (u64)(nbase + r) * K + q * 8;
        }
    }

    auto issue = [&](int kt, int st) {
        const u32 base = sb + (u32)st * C::STG;
        const int ko = kt * BK;
#pragma unroll
        for (int i = 0; i < C::SLOT; i++)
            if (ok_s[i]) cp16(base + dst[i], src[i] + ko);
        asm volatile("cp.async.commit_group;\n");
    };

    issue(0, 0); issue(1, 1); issue(2, 2);

    const int warp = tid >> 5, lane = tid & 31;
    const int g = lane >> 2, tg = lane & 3;
    const int wm = warp & 3, wn = warp >> 2;    // 4(M) x 2(N)

    float c[2][C::NF][4];
#pragma unroll
    for (int mf = 0; mf < 2; mf++)
#pragma unroll
        for (int nf = 0; nf < C::NF; nf++)
#pragma unroll
            for (int i = 0; i < 4; i++) c[mf][nf][i] = 0.f;

    const char* smem = dyn_smem;

    for (int kt = 0; kt < KIT; kt++) {
        const int st = kt % STAGES;
        if      (kt <  KIT - 2) asm volatile("cp.async.wait_group 2;\n");
        else if (kt == KIT - 2) asm volatile("cp.async.wait_group 1;\n");
        else                    asm volatile("cp.async.wait_group 0;\n");
        __syncthreads();

        if (kt + 3 < KIT) issue(kt + 3, (kt + 3) % STAGES);

        const char* as = smem + (u32)st * C::STG + (wm * 32 + g) * ROWB;
        const char* bs = smem + (u32)st * C::STG + A_TILEB
                              + (wn * (C::BN / 2) + g) * ROWB;
#pragma unroll
        for (int ks = 0; ks < 2; ks++) {            // two k16 steps per BK=32
            const int kb = ks * 32 + 4 * tg;        // byte offset of k-pair
            u32 a[2][4];
#pragma unroll
            for (int mf = 0; mf < 2; mf++) {
                const char* ar = as + (mf * 16) * ROWB;
                a[mf][0] = *(const u32*)(ar + kb);
                a[mf][1] = *(const u32*)(ar + 8 * ROWB + kb);
                a[mf][2] = *(const u32*)(ar + kb + 16);
                a[mf][3] = *(const u32*)(ar + 8 * ROWB + kb + 16);
            }
#pragma unroll
            for (int nf = 0; nf < C::NF; nf++) {
                const char* br = bs + (nf * 8) * ROWB;
                u32 b0 = *(const u32*)(br + kb);
                u32 b1 = *(const u32*)(br + kb + 16);
                mma16(c[0][nf], a[0][0], a[0][1], a[0][2], a[0][3], b0, b1);
                mma16(c[1][nf], a[1][0], a[1][1], a[1][2], a[1][3], b0, b1);
            }
        }
    }

    // epilogue
#pragma unroll
    for (int mf = 0; mf < 2; mf++) {
        if (EPI == 0) {
#pragma unroll
            for (int nf = 0; nf < C::NF; nf++) {
                const int r  = mbase + wm * 32 + mf * 16 + g;
                const int cl = nbase + wn * (C::BN / 2) + nf * 8 + 2 * tg;
                float* cc = c[mf][nf];
                const float b0 = bias[cl], b1 = bias[cl + 1];
                __half2 o;
                o = __floats2half2_rn(tanhf(cc[0] + b0), tanhf(cc[1] + b1));
                *(__half2*)(g_zh + (u64)r * Da + cl) = o;
                o = __floats2half2_rn(tanhf(cc[2] + b0), tanhf(cc[3] + b1));
                *(__half2*)(g_zh + (u64)(r + 8) * Da + cl) = o;
            }
        } else {
            // cc[0..1]: score(label, cl..cl+1); cc[2..3]: w(label, cl..cl+1)
            const int row_u = mbase + wm * 32 + mf * 16 + g;
            const int label = ((row_u >> 4) << 3) + g;
            const bool ok = (label < Ln);
            float sum_part = 0.f, y_part = 0.f;
#pragma unroll
            for (int nf = 0; nf < C::NF; nf++) {
                const int cl = nbase + wn * (C::BN / 2) + nf * 8 + 2 * tg;
                float* cc = c[mf][nf];
                if (ok) {                       // cl < 4000 guaranteed (25x160 exact)
                    const float e0 = __expf(cc[0]);
                    const float e1 = __expf(cc[1]);
                    *(float2*)(dout + ((u64)bz * Ln + label) * Sn + cl) =
                        make_float2(e0, e1);
                    sum_part += e0 + e1;
                    y_part   += e0 * cc[2] + e1 * cc[3];
                }
            }
            sum_part += __shfl_xor_sync(0xffffffffu, sum_part, 1);
            sum_part += __shfl_xor_sync(0xffffffffu, sum_part, 2);
            y_part   += __shfl_xor_sync(0xffffffffu, y_part, 1);
            y_part   += __shfl_xor_sync(0xffffffffu, y_part, 2);
            if (ok && tg == 0) {
                atomicAdd(g_sum  + (u64)bz * Ln + label, sum_part);
                atomicAdd(g_ynum + (u64)bz * Ln + label, y_part);
            }
        }
    }
}

// ---- finalize: scale unnormalized alpha in place; emit y ----
// Reversed block order: rows written last by gemm2 are read first (L2-warm).
__global__ void __launch_bounds__(256)
finalize_k(float* __restrict__ dout, const float* __restrict__ Vb) {
    const int bid = (int)gridDim.x - 1 - (int)blockIdx.x;
    const int b = bid / Ln;
    const int l = bid - b * Ln;
    float* arow = dout + (u64)Bn * Ln + ((u64)b * Ln + l) * Sn;
    const int tid = threadIdx.x;

    const float inv = 1.f / g_sum[(u64)b * Ln + l];
    if (tid == 0)
        dout[(u64)b * Ln + l] = g_ynum[(u64)b * Ln + l] * inv + Vb[l];

    const int base = tid * 4;
#pragma unroll
    for (int j = 0; j < 4; j++) {
        const int i = base + j * 1024;
        if (i < Sn) {
            float4 v = *(const float4*)(arow + i);
            v.x *= inv; v.y *= inv; v.z *= inv; v.w *= inv;
            *(float4*)(arow + i) = v;
        }
    }
}

// ---- launch ----
extern "C" void kernel_launch(void* const* d_in, const int* in_sizes, int n_in,
                              void* d_out, int out_size) {
    const float* x  = (const float*)d_in[0];
    const float* Ww = (const float*)d_in[1];
    const float* Wb = (const float*)d_in[2];
    const float* Uw = (const float*)d_in[3];
    const float* Vw = (const float*)d_in[4];
    const float* Vb = (const float*)d_in[5];
    float* out = (float*)d_out;

    cudaFuncSetAttribute(gemm_k<0>, cudaFuncAttributeMaxDynamicSharedMemorySize,
                         (int)Cfg<0>::SME);
    cudaFuncSetAttribute(gemm_k<1>, cudaFuncAttributeMaxDynamicSharedMemorySize,
                         (int)Cfg<1>::SME);

    // convert inputs to fp16 (float4 element counts); sel==1 also zeroes accumulators
    round_k<<<(4096000 + 255) / 256, 256>>>(x,  4096000, 0);
    round_k<<<( 131072 + 255) / 256, 256>>>(Ww,  131072, 1);
    round_k<<<(1141888 + 255) / 256, 256>>>(Uw, 1141888, 2);
    round_k<<<(1141888 + 255) / 256, 256>>>(Vw, 1141888, 3);

    // z = tanh(x W^T + b) -> g_zh
    gemm_k<0><<<dim3(4, 125, 1), 256, Cfg<0>::SME>>>(Wb, nullptr);
    // fused scores/w GEMM (BN=160, 25 exact N-tiles): exp -> alpha region; atomics
    gemm_k<1><<<dim3(25, 140, 4), 256, Cfg<1>::SME>>>(nullptr, out + (u64)Bn * Ln);
    // normalize alpha in place + y
    finalize_k<<<Bn * Ln, 256>>>(out, Vb);
}